// round 14
// baseline (speedup 1.0000x reference)
#include <cuda_runtime.h>
#include <cuda_fp16.h>
#include <cstdint>
#include <math.h>

#define BB 2
#define CC 64
#define HH 96
#define WIMG 96
#define NN 9216
#define BN (BB*NN)
#define NI 144
#define KSPL 2
#define IPS (NI/KSPL)    // 72 iters per split
#define XST 66           // smem pixel-tile stride

__device__ __align__(16) __half g_q[BB*NN*CC];   // pre-scaled by log2(e)
__device__ __align__(16) __half g_k[BB*NN*CC];
__device__ __align__(16) __half g_v[BB*NN*CC];
__device__ __align__(16) float  g_oP[KSPL*BB*NN*CC];  // partial O (unnormalized)
__device__ __align__(16) float  g_lP[KSPL*BB*NN];     // partial row sums
__device__ __align__(16) float  g_x1[BB*CC*NN];
__device__ __align__(16) float  g_h [BB*CC*NN];
__device__ __align__(16) float  g_h2[BB*CC*NN];
__device__               float  g_gk[CC*64];

// ---------------- Kernel 0: spectral filter -> 8x8 circular kernel ---------
__global__ void k_spec(const float* __restrict__ fw)
{
    int c = threadIdx.x;
    const float ct[8] = {1.f, 0.70710678118654752f, 0.f, -0.70710678118654752f,
                        -1.f, -0.70710678118654752f, 0.f, 0.70710678118654752f};
    const float st[8] = {0.f, 0.70710678118654752f, 1.f, 0.70710678118654752f,
                         0.f, -0.70710678118654752f, -1.f, -0.70710678118654752f};
    float Cv[5][8], Sv[5][8];
    for (int v = 0; v < 5; v++)
        for (int d = 0; d < 8; d++) {
            float cs = 0.f, sn = 0.f;
            for (int u = 0; u < 8; u++) {
                float w = fw[c*40 + u*5 + v];
                int k = (u*d) & 7;
                cs += w * ct[k]; sn += w * st[k];
            }
            Cv[v][d] = cs; Sv[v][d] = sn;
        }
    for (int d = 0; d < 8; d++)
        for (int e = 0; e < 8; e++) {
            float acc = Cv[0][d] + ((e & 1) ? -Cv[4][d] : Cv[4][d]);
            for (int v = 1; v <= 3; v++) {
                int k = (v*e) & 7;
                acc += 2.f * (Cv[v][d]*ct[k] - Sv[v][d]*st[k]);
            }
            g_gk[c*64 + d*8 + e] = acc * (1.f/64.f);
        }
}

// ---------------- Kernel 1: LN1 + QKV, 64-px tile, 4 thr/px ----------------
__global__ void __launch_bounds__(256) k_ln_qkv(const float* __restrict__ x,
    const float* __restrict__ lnw, const float* __restrict__ lnb,
    const float* __restrict__ qw, const float* __restrict__ qb,
    const float* __restrict__ kw, const float* __restrict__ kb,
    const float* __restrict__ vw, const float* __restrict__ vb)
{
    __shared__ float xs[CC*XST];
    __shared__ float sW[CC*CC];
    __shared__ float sB[CC], sLw[CC], sLb[CC];
    int tid = threadIdx.x;
    int blk = blockIdx.x;
    int b = blk / (NN/64);
    int n0 = (blk % (NN/64)) * 64;

    {
        const float* xb = x + (size_t)b * CC * NN + n0;
        int pxl = tid & 63;
        for (int c = tid >> 6; c < CC; c += 4)
            xs[c*XST + pxl] = xb[(size_t)c * NN + pxl];
    }
    if (tid < CC) { sLw[tid] = lnw[tid]; sLb[tid] = lnb[tid]; }
    __syncthreads();

    int px = tid >> 2, sub = tid & 3;
    int cb = sub * 16;
    float xv[16];
    float mu = 0.f;
#pragma unroll
    for (int j = 0; j < 16; j++) { xv[j] = xs[(cb + j)*XST + px]; mu += xv[j]; }
    mu += __shfl_xor_sync(0xffffffffu, mu, 1);
    mu += __shfl_xor_sync(0xffffffffu, mu, 2);
    mu *= (1.f / CC);
    float var = 0.f;
#pragma unroll
    for (int j = 0; j < 16; j++) { float d = xv[j] - mu; var += d * d; }
    var += __shfl_xor_sync(0xffffffffu, var, 1);
    var += __shfl_xor_sync(0xffffffffu, var, 2);
    float rstd = rsqrtf(var * (1.f / CC) + 1e-5f);
#pragma unroll
    for (int j = 0; j < 16; j++)
        xs[(cb + j)*XST + px] = (xv[j] - mu) * rstd * sLw[cb + j] + sLb[cb + j];

    const float* Wp[3] = {qw, kw, vw};
    const float* Bp[3] = {qb, kb, vb};
    __half* Op[3] = {g_q, g_k, g_v};
#pragma unroll 1
    for (int m = 0; m < 3; m++) {
        __syncthreads();
        for (int i = tid; i < CC*CC; i += 256) sW[i] = Wp[m][i];
        if (tid < CC) sB[tid] = Bp[m][tid];
        __syncthreads();
        float sc = (m == 0) ? 1.4426950408889634f : 1.0f;
        __half2* op = (__half2*)(Op[m] + ((size_t)b * NN + n0 + px) * CC);
#pragma unroll 1
        for (int oo = 0; oo < 16; oo += 2) {
            int o = cb + oo;
            float a0 = sB[o], a1 = sB[o + 1];
            const float* w0 = &sW[o * CC];
            const float* w1 = &sW[(o + 1) * CC];
#pragma unroll
            for (int c = 0; c < CC; c++) {
                float xc = xs[c*XST + px];
                a0 = fmaf(w0[c], xc, a0);
                a1 = fmaf(w1[c], xc, a1);
            }
            op[o >> 1] = __floats2half2_rn(a0 * sc, a1 * sc);
        }
    }
}

// ---------------- Kernel 2: flash attention, f16-acc QK, occ 4 (R11) -------
__device__ __forceinline__ uint32_t smem_u32(const void* p) {
    return (uint32_t)__cvta_generic_to_shared(p);
}
__device__ __forceinline__ void cp16(uint32_t dst, const void* src) {
    asm volatile("cp.async.cg.shared.global [%0], [%1], 16;\n" :: "r"(dst), "l"(src));
}
__device__ __forceinline__ int swz(int row, int col) {
    int chunk = col >> 3;
    return row * 64 + ((chunk ^ (row & 7)) << 3) + (col & 7);
}

__global__ void __launch_bounds__(128, 4) k_attn()
{
    extern __shared__ __align__(16) __half smem[];
    __half* sQ = smem;
    __half* sK = smem + 64*64;
    __half* sV = sK + 2*64*64;

    int tid = threadIdx.x;
    int w = tid >> 5, lane = tid & 31;
    int b = blockIdx.y;
    int ks = blockIdx.z;
    int q0 = blockIdx.x * 64;
    int it0 = ks * IPS, itE = it0 + IPS;

    {
        const uint4* gq = (const uint4*)(g_q + ((size_t)b * NN + q0) * CC);
#pragma unroll
        for (int j = 0; j < 4; j++) {
            int i = tid + 128 * j; int r = i >> 3, cbk = i & 7;
            *(uint4*)(sQ + r*64 + ((cbk ^ (r & 7)) << 3)) = gq[i];
        }
    }

    auto prefetch = [&](int t, int st) {
        const char* gk = (const char*)(g_k + ((size_t)b * NN + (size_t)t * 64) * CC);
        const char* gv = (const char*)(g_v + ((size_t)b * NN + (size_t)t * 64) * CC);
        uint32_t kb = smem_u32(sK + st*64*64);
        uint32_t vb = smem_u32(sV + st*64*64);
#pragma unroll
        for (int j = 0; j < 4; j++) {
            int i = tid + 128 * j; int r = i >> 3, cbk = i & 7;
            int off = (r*64 + ((cbk ^ (r & 7)) << 3)) * 2;
            cp16(kb + off, gk + i*16);
            cp16(vb + off, gv + i*16);
        }
        asm volatile("cp.async.commit_group;\n" ::: "memory");
    };
    prefetch(it0, 0);
    prefetch(it0 + 1, 1);
    __syncthreads();

    uint32_t qa[4][4];
    {
        int g8_ = lane & 7;
        int sel_ = lane >> 3;
        int radd = (sel_ & 1) ? 8 : 0;
        int cadd = (sel_ & 2) ? 8 : 0;
#pragma unroll
        for (int kt = 0; kt < 4; kt++) {
            int row = w*16 + radd + g8_;
            int col = kt*16 + cadd;
            uint32_t a = smem_u32(sQ + swz(row, col));
            asm volatile("ldmatrix.sync.aligned.m8n8.x4.shared.b16 {%0,%1,%2,%3},[%4];"
                : "=r"(qa[kt][0]), "=r"(qa[kt][1]), "=r"(qa[kt][2]), "=r"(qa[kt][3])
                : "r"(a));
        }
    }

    float o[8][4];
    float lacc0 = 0.f, lacc1 = 0.f;
#pragma unroll
    for (int i = 0; i < 8; i++)
#pragma unroll
        for (int j = 0; j < 4; j++) o[i][j] = 0.f;

    int g8 = lane & 7;
    int sel = lane >> 3;
    int sel2 = lane >> 4;
    const uint32_t BIAS8 = 0xC800C800u;

#pragma unroll 1
    for (int it = it0; it < itE; it++) {
        if (it + 1 < itE) asm volatile("cp.async.wait_group 1;" ::: "memory");
        else              asm volatile("cp.async.wait_group 0;" ::: "memory");
        __syncthreads();
        const __half* bK = sK + (it & 1) * 64*64;
        const __half* bV = sV + (it & 1) * 64*64;

        uint32_t sh[8][2];
#pragma unroll
        for (int nt = 0; nt < 8; nt++) { sh[nt][0] = 0u; sh[nt][1] = 0u; }
#pragma unroll
        for (int kk = 0; kk < 4; kk++) {
#pragma unroll
            for (int ntp = 0; ntp < 4; ntp++) {
                uint32_t b0, b1, b2, b3;
                int row = (2*ntp + (sel >> 1))*8 + g8;
                int col = kk*16 + (sel & 1)*8;
                uint32_t a = smem_u32(bK + swz(row, col));
                asm volatile("ldmatrix.sync.aligned.m8n8.x4.shared.b16 {%0,%1,%2,%3},[%4];"
                    : "=r"(b0), "=r"(b1), "=r"(b2), "=r"(b3) : "r"(a));
                asm volatile("mma.sync.aligned.m16n8k16.row.col.f16.f16.f16.f16 "
                    "{%0,%1},{%2,%3,%4,%5},{%6,%7},{%0,%1};"
                    : "+r"(sh[2*ntp][0]), "+r"(sh[2*ntp][1])
                    : "r"(qa[kk][0]), "r"(qa[kk][1]), "r"(qa[kk][2]), "r"(qa[kk][3]),
                      "r"(b0), "r"(b1));
                asm volatile("mma.sync.aligned.m16n8k16.row.col.f16.f16.f16.f16 "
                    "{%0,%1},{%2,%3,%4,%5},{%6,%7},{%0,%1};"
                    : "+r"(sh[2*ntp+1][0]), "+r"(sh[2*ntp+1][1])
                    : "r"(qa[kk][0]), "r"(qa[kk][1]), "r"(qa[kk][2]), "r"(qa[kk][3]),
                      "r"(b2), "r"(b3));
            }
        }

        uint32_t ph[8][2];
        uint32_t a0h = 0, a1h = 0;
#pragma unroll
        for (int nt = 0; nt < 8; nt++) {
            uint32_t r01, r23;
            asm("add.rn.f16x2 %0, %1, %2;" : "=r"(r01) : "r"(sh[nt][0]), "r"(BIAS8));
            asm("add.rn.f16x2 %0, %1, %2;" : "=r"(r23) : "r"(sh[nt][1]), "r"(BIAS8));
            asm("ex2.approx.f16x2 %0, %1;" : "=r"(r01) : "r"(r01));
            asm("ex2.approx.f16x2 %0, %1;" : "=r"(r23) : "r"(r23));
            ph[nt][0] = r01; ph[nt][1] = r23;
            asm("add.rn.f16x2 %0, %0, %1;" : "+r"(a0h) : "r"(r01));
            asm("add.rn.f16x2 %0, %0, %1;" : "+r"(a1h) : "r"(r23));
        }
        {
            float2 f0 = __half22float2(*(__half2*)&a0h);
            float2 f1 = __half22float2(*(__half2*)&a1h);
            lacc0 += f0.x + f0.y;
            lacc1 += f1.x + f1.y;
        }

#pragma unroll
        for (int kt = 0; kt < 4; kt++) {
            uint32_t a0 = ph[2*kt][0], a1 = ph[2*kt][1];
            uint32_t a2 = ph[2*kt+1][0], a3 = ph[2*kt+1][1];
#pragma unroll
            for (int ntp = 0; ntp < 4; ntp++) {
                uint32_t b0, b1, b2, b3;
                int row = kt*16 + (lane & 15);
                int col = (2*ntp + sel2)*8;
                uint32_t a = smem_u32(bV + swz(row, col));
                asm volatile("ldmatrix.sync.aligned.m8n8.x4.trans.shared.b16 {%0,%1,%2,%3},[%4];"
                    : "=r"(b0), "=r"(b1), "=r"(b2), "=r"(b3) : "r"(a));
                asm volatile("mma.sync.aligned.m16n8k16.row.col.f32.f16.f16.f32 "
                    "{%0,%1,%2,%3},{%4,%5,%6,%7},{%8,%9},{%0,%1,%2,%3};"
                    : "+f"(o[2*ntp][0]), "+f"(o[2*ntp][1]), "+f"(o[2*ntp][2]), "+f"(o[2*ntp][3])
                    : "r"(a0), "r"(a1), "r"(a2), "r"(a3), "r"(b0), "r"(b1));
                asm volatile("mma.sync.aligned.m16n8k16.row.col.f32.f16.f16.f32 "
                    "{%0,%1,%2,%3},{%4,%5,%6,%7},{%8,%9},{%0,%1,%2,%3};"
                    : "+f"(o[2*ntp+1][0]), "+f"(o[2*ntp+1][1]), "+f"(o[2*ntp+1][2]), "+f"(o[2*ntp+1][3])
                    : "r"(a0), "r"(a1), "r"(a2), "r"(a3), "r"(b2), "r"(b3));
            }
        }
        __syncthreads();
        if (it + 2 < itE) prefetch(it + 2, it & 1);
    }

    lacc0 += __shfl_xor_sync(0xffffffffu, lacc0, 1);
    lacc0 += __shfl_xor_sync(0xffffffffu, lacc0, 2);
    lacc1 += __shfl_xor_sync(0xffffffffu, lacc1, 1);
    lacc1 += __shfl_xor_sync(0xffffffffu, lacc1, 2);
    int g = lane >> 2, qd = lane & 3;
    int row0 = q0 + w*16 + g;
    int row1 = row0 + 8;
    float* Ob = g_oP + ((size_t)(ks*BB + b) * NN) * CC;
#pragma unroll
    for (int nt = 0; nt < 8; nt++) {
        int c = nt*8 + 2*qd;
        *(float2*)&Ob[(size_t)row0*CC + c] = make_float2(o[nt][0], o[nt][1]);
        *(float2*)&Ob[(size_t)row1*CC + c] = make_float2(o[nt][2], o[nt][3]);
    }
    if (qd == 0) {
        g_lP[(size_t)(ks*BB + b) * NN + row0] = lacc0;
        g_lP[(size_t)(ks*BB + b) * NN + row1] = lacc1;
    }
}

// ---------------- Kernel 3: merge + residual + LN2 + proj_in, tiled --------
__global__ void __launch_bounds__(256) k_res_ln_proj(const float* __restrict__ x,
    const float* __restrict__ lnw, const float* __restrict__ lnb,
    const float* __restrict__ pw)
{
    __shared__ float xs[CC*XST];   // normalized values
    __shared__ float ts[CC*XST];   // x+attn, then h transpose buffer
    __shared__ float sW[CC*CC];
    __shared__ float sLw[CC], sLb[CC];
    int tid = threadIdx.x;
    int blk = blockIdx.x;
    int b = blk / (NN/64);
    int n0 = (blk % (NN/64)) * 64;
    int pxl = tid & 63;

    {
        const float* xb = x + (size_t)b * CC * NN + n0;
        for (int c = tid >> 6; c < CC; c += 4)
            ts[c*XST + pxl] = xb[(size_t)c * NN + pxl];
    }
    for (int i = tid; i < CC*CC; i += 256) sW[i] = pw[i];
    if (tid < CC) { sLw[tid] = lnw[tid]; sLb[tid] = lnb[tid]; }
    __syncthreads();

    int px = tid >> 2, sub = tid & 3;
    int n = n0 + px;
    int cb = sub * 16;
    float invl = 1.f / (g_lP[(size_t)(0*BB + b)*NN + n] + g_lP[(size_t)(1*BB + b)*NN + n]);
    const float4* oA = (const float4*)(g_oP + ((size_t)(0*BB + b) * NN + n) * CC + cb);
    const float4* oB = (const float4*)(g_oP + ((size_t)(1*BB + b) * NN + n) * CC + cb);
    float tv[16];
    float mu = 0.f;
#pragma unroll
    for (int j4 = 0; j4 < 4; j4++) {
        float4 va = oA[j4], vb = oB[j4];
        int j = j4 * 4;
        tv[j+0] = ts[(cb+j+0)*XST + px] + (va.x + vb.x) * invl;
        tv[j+1] = ts[(cb+j+1)*XST + px] + (va.y + vb.y) * invl;
        tv[j+2] = ts[(cb+j+2)*XST + px] + (va.z + vb.z) * invl;
        tv[j+3] = ts[(cb+j+3)*XST + px] + (va.w + vb.w) * invl;
        mu += tv[j+0] + tv[j+1] + tv[j+2] + tv[j+3];
    }
#pragma unroll
    for (int j = 0; j < 16; j++) ts[(cb+j)*XST + px] = tv[j];
    mu += __shfl_xor_sync(0xffffffffu, mu, 1);
    mu += __shfl_xor_sync(0xffffffffu, mu, 2);
    mu *= (1.f / CC);
    float var = 0.f;
#pragma unroll
    for (int j = 0; j < 16; j++) { float d = tv[j] - mu; var += d * d; }
    var += __shfl_xor_sync(0xffffffffu, var, 1);
    var += __shfl_xor_sync(0xffffffffu, var, 2);
    float rstd = rsqrtf(var * (1.f / CC) + 1e-5f);
#pragma unroll
    for (int j = 0; j < 16; j++)
        xs[(cb+j)*XST + px] = (tv[j] - mu) * rstd * sLw[cb+j] + sLb[cb+j];
    __syncthreads();

    // x1 coalesced write (reads ts) + matvec (reads xs)
    {
        float* x1b = g_x1 + (size_t)b * CC * NN + n0;
        for (int c = tid >> 6; c < CC; c += 4)
            x1b[(size_t)c * NN + pxl] = ts[c*XST + pxl];
    }
    float acc[16];
#pragma unroll 1
    for (int oo = 0; oo < 16; oo += 2) {
        int o = cb + oo;
        float a0 = 0.f, a1 = 0.f;
        const float* w0 = &sW[o * CC];
        const float* w1 = &sW[(o + 1) * CC];
#pragma unroll
        for (int c = 0; c < CC; c++) {
            float xc = xs[c*XST + px];
            a0 = fmaf(w0[c], xc, a0);
            a1 = fmaf(w1[c], xc, a1);
        }
        acc[oo] = a0; acc[oo+1] = a1;
    }
    __syncthreads();   // x1 reads of ts complete
#pragma unroll
    for (int j = 0; j < 16; j++) ts[(cb+j)*XST + px] = acc[j];
    __syncthreads();
    {
        float* hb = g_h + (size_t)b * CC * NN + n0;
        for (int c = tid >> 6; c < CC; c += 4)
            hb[(size_t)c * NN + pxl] = ts[c*XST + pxl];
    }
}

// ---------------- Kernel 4: per-patch 8x8 circular conv, register-blocked --
__global__ void __launch_bounds__(512) k_fftconv()
{
    __shared__ float sin_[CC*72];
    __shared__ float sg[CC*72];
    int tid = threadIdx.x;
    int blk = blockIdx.x;
    int b = blk / 144;
    int pr = (blk / 12) % 12, pc = blk % 12;
    for (int i = tid; i < CC*64; i += 512) {
        int c = i >> 6, pos = i & 63;
        int y = pr*8 + (pos >> 3), x = pc*8 + (pos & 7);
        sin_[c*72 + pos] = g_h[(size_t)(b*CC + c)*NN + y*WIMG + x];
        sg[c*72 + pos] = g_gk[i];
    }
    __syncthreads();

    int c = tid >> 3;
    int n = tid & 7;
    float acc[8];
#pragma unroll
    for (int m = 0; m < 8; m++) acc[m] = 0.f;

#pragma unroll
    for (int pp = 0; pp < 8; pp++) {
        int grow = (n - pp) & 7;
        const float* gr = &sg[c*72 + grow*8];
        float gv[8] = {gr[0], gr[1], gr[2], gr[3], gr[4], gr[5], gr[6], gr[7]};
        const float* ir = &sin_[c*72 + pp*8];
#pragma unroll
        for (int qq = 0; qq < 8; qq++) {
            float iv = ir[qq];
#pragma unroll
            for (int m = 0; m < 8; m++)
                acc[m] = fmaf(iv, gv[(m - qq) & 7], acc[m]);
        }
    }

    int y = pr*8 + n;
    float* dst = &g_h2[(size_t)(b*CC + c)*NN + y*WIMG + pc*8];
    *(float4*)(dst    ) = make_float4(acc[0], acc[1], acc[2], acc[3]);
    *(float4*)(dst + 4) = make_float4(acc[4], acc[5], acc[6], acc[7]);
}

// ---------------- Kernel 5: dw3x3 + GELU gate + proj_out (channel-split) ---
__device__ __forceinline__ float dw3x3(const float* __restrict__ base,
                                       int y, int x, const float* __restrict__ w9)
{
    float acc = 0.f;
#pragma unroll
    for (int dy = -1; dy <= 1; dy++) {
        int yy = y + dy;
        if ((unsigned)yy >= HH) continue;
#pragma unroll
        for (int dx = -1; dx <= 1; dx++) {
            int xx = x + dx;
            if ((unsigned)xx >= WIMG) continue;
            acc = fmaf(base[yy*WIMG + xx], w9[(dy+1)*3 + (dx+1)], acc);
        }
    }
    return acc;
}

__global__ void k_final(const float* __restrict__ dw,
                        const float* __restrict__ pw,
                        float* __restrict__ out)
{
    __shared__ float sW[CC*32];
    __shared__ float sD[CC*9];
    int tid = threadIdx.x;
    for (int i = tid; i < CC*32; i += 256) sW[i] = pw[i];
    for (int i = tid; i < CC*9; i += 256) sD[i] = dw[i];
    __syncthreads();
    int p = blockIdx.x * 128 + (tid >> 1);
    int hf = tid & 1;
    int b = p / NN, n = p % NN;
    int y = n / WIMG, x = n % WIMG;

    float gv[32];
#pragma unroll
    for (int c = 0; c < 32; c++) {
        const float* b1 = g_h2 + (size_t)(b*CC + c) * NN;
        const float* b2 = g_h2 + (size_t)(b*CC + c + 32) * NN;
        float h1 = dw3x3(b1, y, x, &sD[c*9]);
        float h2 = dw3x3(b2, y, x, &sD[(c+32)*9]);
        float gl = 0.5f * h1 * (1.f + erff(h1 * 0.70710678118654752f));
        gv[c] = gl * h2;
    }
    int obase = hf * 32;
#pragma unroll 1
    for (int oo = 0; oo < 32; oo += 2) {
        int o = obase + oo;
        float a0 = 0.f, a1 = 0.f;
        const float* w0 = &sW[o * 32];
        const float* w1 = &sW[(o + 1) * 32];
#pragma unroll
        for (int c = 0; c < 32; c++) {
            a0 = fmaf(w0[c], gv[c], a0);
            a1 = fmaf(w1[c], gv[c], a1);
        }
        out[(size_t)(b*CC + o    )*NN + n] = g_x1[(size_t)(b*CC + o    )*NN + n] + a0;
        out[(size_t)(b*CC + o + 1)*NN + n] = g_x1[(size_t)(b*CC + o + 1)*NN + n] + a1;
    }
}

// ---------------------------------------------------------------------------
extern "C" void kernel_launch(void* const* d_in, const int* in_sizes, int n_in,
                              void* d_out, int out_size)
{
    const float* x    = (const float*)d_in[0];
    const float* ln1w = (const float*)d_in[1];
    const float* ln1b = (const float*)d_in[2];
    const float* ln2w = (const float*)d_in[3];
    const float* ln2b = (const float*)d_in[4];
    const float* qw   = (const float*)d_in[5];
    const float* qb   = (const float*)d_in[6];
    const float* kw   = (const float*)d_in[7];
    const float* kb   = (const float*)d_in[8];
    const float* vw   = (const float*)d_in[9];
    const float* vb   = (const float*)d_in[10];
    const float* fftw = (const float*)d_in[11];
    const float* piw  = (const float*)d_in[12];
    const float* dww  = (const float*)d_in[13];
    const float* poww = (const float*)d_in[14];
    float* out = (float*)d_out;

    const int attn_smem = (5 * 64 * 64) * (int)sizeof(__half);
    cudaFuncSetAttribute(k_attn, cudaFuncAttributeMaxDynamicSharedMemorySize, attn_smem);

    k_spec<<<1, 64>>>(fftw);
    k_ln_qkv<<<BN/64, 256>>>(x, ln1w, ln1b, qw, qb, kw, kb, vw, vb);
    k_attn<<<dim3(NN/64, BB, KSPL), 128, attn_smem>>>();
    k_res_ln_proj<<<BN/64, 256>>>(x, ln2w, ln2b, piw);
    k_fftconv<<<BB*144, 512>>>();
    k_final<<<BN/128, 256>>>(dww, poww, out);
}

// round 15
// speedup vs baseline: 1.4887x; 1.4887x over previous
#include <cuda_runtime.h>
#include <cuda_fp16.h>
#include <cstdint>
#include <math.h>

#define BB 2
#define CC 64
#define HH 96
#define WIMG 96
#define NN 9216
#define BN (BB*NN)
#define NI 144
#define KSPL 2
#define IPS (NI/KSPL)    // 72 iters per split

__device__ __align__(16) __half g_q[BB*NN*CC];   // pre-scaled by log2(e)
__device__ __align__(16) __half g_k[BB*NN*CC];
__device__ __align__(16) __half g_v[BB*NN*CC];
__device__ __align__(16) float  g_oP[KSPL*BB*NN*CC];  // partial O (unnormalized)
__device__ __align__(16) float  g_lP[KSPL*BB*NN];     // partial row sums
__device__ __align__(16) float  g_x1[BB*CC*NN];
__device__ __align__(16) float  g_h [BB*CC*NN];
__device__ __align__(16) float  g_h2[BB*CC*NN];
__device__               float  g_gk[CC*64];

// ---------------- Kernel 0: spectral filter -> 8x8 circular kernel ---------
__global__ void k_spec(const float* __restrict__ fw)
{
    int c = threadIdx.x;
    const float ct[8] = {1.f, 0.70710678118654752f, 0.f, -0.70710678118654752f,
                        -1.f, -0.70710678118654752f, 0.f, 0.70710678118654752f};
    const float st[8] = {0.f, 0.70710678118654752f, 1.f, 0.70710678118654752f,
                         0.f, -0.70710678118654752f, -1.f, -0.70710678118654752f};
    float Cv[5][8], Sv[5][8];
    for (int v = 0; v < 5; v++)
        for (int d = 0; d < 8; d++) {
            float cs = 0.f, sn = 0.f;
            for (int u = 0; u < 8; u++) {
                float w = fw[c*40 + u*5 + v];
                int k = (u*d) & 7;
                cs += w * ct[k]; sn += w * st[k];
            }
            Cv[v][d] = cs; Sv[v][d] = sn;
        }
    for (int d = 0; d < 8; d++)
        for (int e = 0; e < 8; e++) {
            float acc = Cv[0][d] + ((e & 1) ? -Cv[4][d] : Cv[4][d]);
            for (int v = 1; v <= 3; v++) {
                int k = (v*e) & 7;
                acc += 2.f * (Cv[v][d]*ct[k] - Sv[v][d]*st[k]);
            }
            g_gk[c*64 + d*8 + e] = acc * (1.f/64.f);
        }
}

// ---------------- Kernel 1: LN1 + QKV (q scaled by log2 e) -----------------
__global__ void k_ln_qkv(const float* __restrict__ x,
    const float* __restrict__ lnw, const float* __restrict__ lnb,
    const float* __restrict__ qw, const float* __restrict__ qb,
    const float* __restrict__ kw, const float* __restrict__ kb,
    const float* __restrict__ vw, const float* __restrict__ vb)
{
    __shared__ float sW[CC*CC];
    __shared__ float sB[CC], sLw[CC], sLb[CC];
    int tid = threadIdx.x;
    if (tid < CC) { sLw[tid] = lnw[tid]; sLb[tid] = lnb[tid]; }
    __syncthreads();
    int p = blockIdx.x * 128 + (tid >> 1);
    int hf = tid & 1;
    int b = p / NN, n = p % NN;
    const float* xb = x + (size_t)b * CC * NN + n;
    float xv[CC];
    float mu = 0.f;
#pragma unroll
    for (int c = 0; c < CC; c++) { xv[c] = xb[(size_t)c * NN]; mu += xv[c]; }
    mu *= (1.f / CC);
    float var = 0.f;
#pragma unroll
    for (int c = 0; c < CC; c++) { float d = xv[c] - mu; var += d * d; }
    float rstd = rsqrtf(var * (1.f / CC) + 1e-5f);
#pragma unroll
    for (int c = 0; c < CC; c++) xv[c] = (xv[c] - mu) * rstd * sLw[c] + sLb[c];

    const float* Wp[3] = {qw, kw, vw};
    const float* Bp[3] = {qb, kb, vb};
    __half* Op[3] = {g_q, g_k, g_v};
    int obase = hf * 32;
#pragma unroll 1
    for (int m = 0; m < 3; m++) {
        __syncthreads();
        for (int i = tid; i < CC*CC; i += 256) sW[i] = Wp[m][i];
        if (tid < CC) sB[tid] = Bp[m][tid];
        __syncthreads();
        float sc = (m == 0) ? 1.4426950408889634f : 1.0f;
        __half2* op = (__half2*)(Op[m] + (size_t)p * CC);
#pragma unroll 1
        for (int oo = 0; oo < 32; oo += 4) {
            int o = obase + oo;
            float a0 = sB[o], a1 = sB[o+1], a2 = sB[o+2], a3 = sB[o+3];
            const float* w0 = &sW[(o  ) * CC];
            const float* w1 = &sW[(o+1) * CC];
            const float* w2 = &sW[(o+2) * CC];
            const float* w3 = &sW[(o+3) * CC];
#pragma unroll
            for (int c = 0; c < CC; c++) {
                float xc = xv[c];
                a0 = fmaf(w0[c], xc, a0);
                a1 = fmaf(w1[c], xc, a1);
                a2 = fmaf(w2[c], xc, a2);
                a3 = fmaf(w3[c], xc, a3);
            }
            op[(o >> 1)    ] = __floats2half2_rn(a0 * sc, a1 * sc);
            op[(o >> 1) + 1] = __floats2half2_rn(a2 * sc, a3 * sc);
        }
    }
}

// ---------------- Kernel 2: flash attention, f16-acc QK, occ 4 (R11) -------
__device__ __forceinline__ uint32_t smem_u32(const void* p) {
    return (uint32_t)__cvta_generic_to_shared(p);
}
__device__ __forceinline__ void cp16(uint32_t dst, const void* src) {
    asm volatile("cp.async.cg.shared.global [%0], [%1], 16;\n" :: "r"(dst), "l"(src));
}
__device__ __forceinline__ int swz(int row, int col) {
    int chunk = col >> 3;
    return row * 64 + ((chunk ^ (row & 7)) << 3) + (col & 7);
}

__global__ void __launch_bounds__(128, 4) k_attn()
{
    extern __shared__ __align__(16) __half smem[];
    __half* sQ = smem;                 // 64*64 swizzled
    __half* sK = smem + 64*64;         // 2 stages x 64*64
    __half* sV = sK + 2*64*64;         // 2 stages x 64*64

    int tid = threadIdx.x;
    int w = tid >> 5, lane = tid & 31;
    int b = blockIdx.y;
    int ks = blockIdx.z;
    int q0 = blockIdx.x * 64;
    int it0 = ks * IPS, itE = it0 + IPS;

    {
        const uint4* gq = (const uint4*)(g_q + ((size_t)b * NN + q0) * CC);
#pragma unroll
        for (int j = 0; j < 4; j++) {
            int i = tid + 128 * j; int r = i >> 3, cbk = i & 7;
            *(uint4*)(sQ + r*64 + ((cbk ^ (r & 7)) << 3)) = gq[i];
        }
    }

    auto prefetch = [&](int t, int st) {
        const char* gk = (const char*)(g_k + ((size_t)b * NN + (size_t)t * 64) * CC);
        const char* gv = (const char*)(g_v + ((size_t)b * NN + (size_t)t * 64) * CC);
        uint32_t kb = smem_u32(sK + st*64*64);
        uint32_t vb = smem_u32(sV + st*64*64);
#pragma unroll
        for (int j = 0; j < 4; j++) {
            int i = tid + 128 * j; int r = i >> 3, cbk = i & 7;
            int off = (r*64 + ((cbk ^ (r & 7)) << 3)) * 2;
            cp16(kb + off, gk + i*16);
            cp16(vb + off, gv + i*16);
        }
        asm volatile("cp.async.commit_group;\n" ::: "memory");
    };
    prefetch(it0, 0);
    prefetch(it0 + 1, 1);
    __syncthreads();

    uint32_t qa[4][4];
    {
        int g8_ = lane & 7;
        int sel_ = lane >> 3;
        int radd = (sel_ & 1) ? 8 : 0;
        int cadd = (sel_ & 2) ? 8 : 0;
#pragma unroll
        for (int kt = 0; kt < 4; kt++) {
            int row = w*16 + radd + g8_;
            int col = kt*16 + cadd;
            uint32_t a = smem_u32(sQ + swz(row, col));
            asm volatile("ldmatrix.sync.aligned.m8n8.x4.shared.b16 {%0,%1,%2,%3},[%4];"
                : "=r"(qa[kt][0]), "=r"(qa[kt][1]), "=r"(qa[kt][2]), "=r"(qa[kt][3])
                : "r"(a));
        }
    }

    float o[8][4];
    float lacc0 = 0.f, lacc1 = 0.f;
#pragma unroll
    for (int i = 0; i < 8; i++)
#pragma unroll
        for (int j = 0; j < 4; j++) o[i][j] = 0.f;

    int g8 = lane & 7;
    int sel = lane >> 3;
    int sel2 = lane >> 4;
    const uint32_t BIAS8 = 0xC800C800u;   // f16x2 {-8, -8}

#pragma unroll 1
    for (int it = it0; it < itE; it++) {
        if (it + 1 < itE) asm volatile("cp.async.wait_group 1;" ::: "memory");
        else              asm volatile("cp.async.wait_group 0;" ::: "memory");
        __syncthreads();
        const __half* bK = sK + (it & 1) * 64*64;
        const __half* bV = sV + (it & 1) * 64*64;

        uint32_t sh[8][2];
#pragma unroll
        for (int nt = 0; nt < 8; nt++) { sh[nt][0] = 0u; sh[nt][1] = 0u; }
#pragma unroll
        for (int kk = 0; kk < 4; kk++) {
#pragma unroll
            for (int ntp = 0; ntp < 4; ntp++) {
                uint32_t b0, b1, b2, b3;
                int row = (2*ntp + (sel >> 1))*8 + g8;
                int col = kk*16 + (sel & 1)*8;
                uint32_t a = smem_u32(bK + swz(row, col));
                asm volatile("ldmatrix.sync.aligned.m8n8.x4.shared.b16 {%0,%1,%2,%3},[%4];"
                    : "=r"(b0), "=r"(b1), "=r"(b2), "=r"(b3) : "r"(a));
                asm volatile("mma.sync.aligned.m16n8k16.row.col.f16.f16.f16.f16 "
                    "{%0,%1},{%2,%3,%4,%5},{%6,%7},{%0,%1};"
                    : "+r"(sh[2*ntp][0]), "+r"(sh[2*ntp][1])
                    : "r"(qa[kk][0]), "r"(qa[kk][1]), "r"(qa[kk][2]), "r"(qa[kk][3]),
                      "r"(b0), "r"(b1));
                asm volatile("mma.sync.aligned.m16n8k16.row.col.f16.f16.f16.f16 "
                    "{%0,%1},{%2,%3,%4,%5},{%6,%7},{%0,%1};"
                    : "+r"(sh[2*ntp+1][0]), "+r"(sh[2*ntp+1][1])
                    : "r"(qa[kk][0]), "r"(qa[kk][1]), "r"(qa[kk][2]), "r"(qa[kk][3]),
                      "r"(b2), "r"(b3));
            }
        }

        uint32_t ph[8][2];
        uint32_t a0h = 0, a1h = 0;
#pragma unroll
        for (int nt = 0; nt < 8; nt++) {
            uint32_t r01, r23;
            asm("add.rn.f16x2 %0, %1, %2;" : "=r"(r01) : "r"(sh[nt][0]), "r"(BIAS8));
            asm("add.rn.f16x2 %0, %1, %2;" : "=r"(r23) : "r"(sh[nt][1]), "r"(BIAS8));
            asm("ex2.approx.f16x2 %0, %1;" : "=r"(r01) : "r"(r01));
            asm("ex2.approx.f16x2 %0, %1;" : "=r"(r23) : "r"(r23));
            ph[nt][0] = r01; ph[nt][1] = r23;
            asm("add.rn.f16x2 %0, %0, %1;" : "+r"(a0h) : "r"(r01));
            asm("add.rn.f16x2 %0, %0, %1;" : "+r"(a1h) : "r"(r23));
        }
        {
            float2 f0 = __half22float2(*(__half2*)&a0h);
            float2 f1 = __half22float2(*(__half2*)&a1h);
            lacc0 += f0.x + f0.y;
            lacc1 += f1.x + f1.y;
        }

#pragma unroll
        for (int kt = 0; kt < 4; kt++) {
            uint32_t a0 = ph[2*kt][0], a1 = ph[2*kt][1];
            uint32_t a2 = ph[2*kt+1][0], a3 = ph[2*kt+1][1];
#pragma unroll
            for (int ntp = 0; ntp < 4; ntp++) {
                uint32_t b0, b1, b2, b3;
                int row = kt*16 + (lane & 15);
                int col = (2*ntp + sel2)*8;
                uint32_t a = smem_u32(bV + swz(row, col));
                asm volatile("ldmatrix.sync.aligned.m8n8.x4.trans.shared.b16 {%0,%1,%2,%3},[%4];"
                    : "=r"(b0), "=r"(b1), "=r"(b2), "=r"(b3) : "r"(a));
                asm volatile("mma.sync.aligned.m16n8k16.row.col.f32.f16.f16.f32 "
                    "{%0,%1,%2,%3},{%4,%5,%6,%7},{%8,%9},{%0,%1,%2,%3};"
                    : "+f"(o[2*ntp][0]), "+f"(o[2*ntp][1]), "+f"(o[2*ntp][2]), "+f"(o[2*ntp][3])
                    : "r"(a0), "r"(a1), "r"(a2), "r"(a3), "r"(b0), "r"(b1));
                asm volatile("mma.sync.aligned.m16n8k16.row.col.f32.f16.f16.f32 "
                    "{%0,%1,%2,%3},{%4,%5,%6,%7},{%8,%9},{%0,%1,%2,%3};"
                    : "+f"(o[2*ntp+1][0]), "+f"(o[2*ntp+1][1]), "+f"(o[2*ntp+1][2]), "+f"(o[2*ntp+1][3])
                    : "r"(a0), "r"(a1), "r"(a2), "r"(a3), "r"(b2), "r"(b3));
            }
        }
        __syncthreads();
        if (it + 2 < itE) prefetch(it + 2, it & 1);
    }

    lacc0 += __shfl_xor_sync(0xffffffffu, lacc0, 1);
    lacc0 += __shfl_xor_sync(0xffffffffu, lacc0, 2);
    lacc1 += __shfl_xor_sync(0xffffffffu, lacc1, 1);
    lacc1 += __shfl_xor_sync(0xffffffffu, lacc1, 2);
    int g = lane >> 2, qd = lane & 3;
    int row0 = q0 + w*16 + g;
    int row1 = row0 + 8;
    float* Ob = g_oP + ((size_t)(ks*BB + b) * NN) * CC;
#pragma unroll
    for (int nt = 0; nt < 8; nt++) {
        int c = nt*8 + 2*qd;
        *(float2*)&Ob[(size_t)row0*CC + c] = make_float2(o[nt][0], o[nt][1]);
        *(float2*)&Ob[(size_t)row1*CC + c] = make_float2(o[nt][2], o[nt][3]);
    }
    if (qd == 0) {
        g_lP[(size_t)(ks*BB + b) * NN + row0] = lacc0;
        g_lP[(size_t)(ks*BB + b) * NN + row1] = lacc1;
    }
}

// ---------------- Kernel 3: merge partials + residual + LN2 + proj_in ------
__global__ void k_res_ln_proj(const float* __restrict__ x,
    const float* __restrict__ lnw, const float* __restrict__ lnb,
    const float* __restrict__ pw)
{
    __shared__ float sW[CC*CC];
    __shared__ float sLw[CC], sLb[CC];
    int tid = threadIdx.x;
    for (int i = tid; i < CC*CC; i += 128) sW[i] = pw[i];
    if (tid < CC) { sLw[tid] = lnw[tid]; sLb[tid] = lnb[tid]; }
    __syncthreads();
    int p = blockIdx.x * 128 + tid;
    int b = p / NN, n = p % NN;
    const float4* oA = (const float4*)(g_oP + (size_t)(0*BB + b) * NN * CC + (size_t)n * CC);
    const float4* oB = (const float4*)(g_oP + (size_t)(1*BB + b) * NN * CC + (size_t)n * CC);
    float invl = 1.f / (g_lP[(size_t)(0*BB + b)*NN + n] + g_lP[(size_t)(1*BB + b)*NN + n]);
    const float* xb = x + (size_t)b * CC * NN + n;
    float* x1b = g_x1 + (size_t)b * CC * NN + n;
    float xv[CC];
    float mu = 0.f;
#pragma unroll
    for (int c4 = 0; c4 < CC/4; c4++) {
        float4 va = oA[c4], vb = oB[c4];
        int c = c4 * 4;
        float t0 = xb[(size_t)(c+0)*NN] + (va.x + vb.x) * invl;
        float t1 = xb[(size_t)(c+1)*NN] + (va.y + vb.y) * invl;
        float t2 = xb[(size_t)(c+2)*NN] + (va.z + vb.z) * invl;
        float t3 = xb[(size_t)(c+3)*NN] + (va.w + vb.w) * invl;
        x1b[(size_t)(c+0)*NN] = t0; x1b[(size_t)(c+1)*NN] = t1;
        x1b[(size_t)(c+2)*NN] = t2; x1b[(size_t)(c+3)*NN] = t3;
        xv[c+0]=t0; xv[c+1]=t1; xv[c+2]=t2; xv[c+3]=t3;
        mu += t0 + t1 + t2 + t3;
    }
    mu *= (1.f / CC);
    float var = 0.f;
#pragma unroll
    for (int c = 0; c < CC; c++) { float d = xv[c] - mu; var += d * d; }
    float rstd = rsqrtf(var * (1.f / CC) + 1e-5f);
#pragma unroll
    for (int c = 0; c < CC; c++) xv[c] = (xv[c] - mu) * rstd * sLw[c] + sLb[c];

    float* hb = g_h + (size_t)b * CC * NN + n;
#pragma unroll 1
    for (int o = 0; o < CC; o += 4) {
        float a0 = 0.f, a1 = 0.f, a2 = 0.f, a3 = 0.f;
        const float* w0 = &sW[(o  ) * CC];
        const float* w1 = &sW[(o+1) * CC];
        const float* w2 = &sW[(o+2) * CC];
        const float* w3 = &sW[(o+3) * CC];
#pragma unroll
        for (int c = 0; c < CC; c++) {
            float xc = xv[c];
            a0 = fmaf(w0[c], xc, a0);
            a1 = fmaf(w1[c], xc, a1);
            a2 = fmaf(w2[c], xc, a2);
            a3 = fmaf(w3[c], xc, a3);
        }
        hb[(size_t)(o+0)*NN] = a0;
        hb[(size_t)(o+1)*NN] = a1;
        hb[(size_t)(o+2)*NN] = a2;
        hb[(size_t)(o+3)*NN] = a3;
    }
}

// ---------------- Kernel 4: per-patch 8x8 circular conv, register-blocked --
__global__ void __launch_bounds__(512) k_fftconv()
{
    __shared__ float sin_[CC*72];
    __shared__ float sg[CC*72];
    int tid = threadIdx.x;
    int blk = blockIdx.x;
    int b = blk / 144;
    int pr = (blk / 12) % 12, pc = blk % 12;
    for (int i = tid; i < CC*64; i += 512) {
        int c = i >> 6, pos = i & 63;
        int y = pr*8 + (pos >> 3), x = pc*8 + (pos & 7);
        sin_[c*72 + pos] = g_h[(size_t)(b*CC + c)*NN + y*WIMG + x];
        sg[c*72 + pos] = g_gk[i];
    }
    __syncthreads();

    int c = tid >> 3;
    int n = tid & 7;
    float acc[8];
#pragma unroll
    for (int m = 0; m < 8; m++) acc[m] = 0.f;

#pragma unroll
    for (int pp = 0; pp < 8; pp++) {
        int grow = (n - pp) & 7;
        const float* gr = &sg[c*72 + grow*8];
        float gv[8] = {gr[0], gr[1], gr[2], gr[3], gr[4], gr[5], gr[6], gr[7]};
        const float* ir = &sin_[c*72 + pp*8];
#pragma unroll
        for (int qq = 0; qq < 8; qq++) {
            float iv = ir[qq];
#pragma unroll
            for (int m = 0; m < 8; m++)
                acc[m] = fmaf(iv, gv[(m - qq) & 7], acc[m]);
        }
    }

    int y = pr*8 + n;
    float* dst = &g_h2[(size_t)(b*CC + c)*NN + y*WIMG + pc*8];
    *(float4*)(dst    ) = make_float4(acc[0], acc[1], acc[2], acc[3]);
    *(float4*)(dst + 4) = make_float4(acc[4], acc[5], acc[6], acc[7]);
}

// ---------------- Kernel 5: dw3x3 + GELU gate + proj_out (channel-split) ---
__device__ __forceinline__ float dw3x3(const float* __restrict__ base,
                                       int y, int x, const float* __restrict__ w9)
{
    float acc = 0.f;
#pragma unroll
    for (int dy = -1; dy <= 1; dy++) {
        int yy = y + dy;
        if ((unsigned)yy >= HH) continue;
#pragma unroll
        for (int dx = -1; dx <= 1; dx++) {
            int xx = x + dx;
            if ((unsigned)xx >= WIMG) continue;
            acc = fmaf(base[yy*WIMG + xx], w9[(dy+1)*3 + (dx+1)], acc);
        }
    }
    return acc;
}

__global__ void k_final(const float* __restrict__ dw,
                        const float* __restrict__ pw,
                        float* __restrict__ out)
{
    __shared__ float sW[CC*32];
    __shared__ float sD[CC*9];
    int tid = threadIdx.x;
    for (int i = tid; i < CC*32; i += 256) sW[i] = pw[i];
    for (int i = tid; i < CC*9; i += 256) sD[i] = dw[i];
    __syncthreads();
    int p = blockIdx.x * 128 + (tid >> 1);
    int hf = tid & 1;
    int b = p / NN, n = p % NN;
    int y = n / WIMG, x = n % WIMG;

    float gv[32];
#pragma unroll
    for (int c = 0; c < 32; c++) {
        const float* b1 = g_h2 + (size_t)(b*CC + c) * NN;
        const float* b2 = g_h2 + (size_t)(b*CC + c + 32) * NN;
        float h1 = dw3x3(b1, y, x, &sD[c*9]);
        float h2 = dw3x3(b2, y, x, &sD[(c+32)*9]);
        float gl = 0.5f * h1 * (1.f + erff(h1 * 0.70710678118654752f));
        gv[c] = gl * h2;
    }
    int obase = hf * 32;
#pragma unroll 1
    for (int oo = 0; oo < 32; oo += 4) {
        int o = obase + oo;
        float a0 = 0.f, a1 = 0.f, a2 = 0.f, a3 = 0.f;
        const float* w0 = &sW[(o  ) * 32];
        const float* w1 = &sW[(o+1) * 32];
        const float* w2 = &sW[(o+2) * 32];
        const float* w3 = &sW[(o+3) * 32];
#pragma unroll
        for (int c = 0; c < 32; c++) {
            float gc = gv[c];
            a0 = fmaf(w0[c], gc, a0);
            a1 = fmaf(w1[c], gc, a1);
            a2 = fmaf(w2[c], gc, a2);
            a3 = fmaf(w3[c], gc, a3);
        }
        out[(size_t)(b*CC + o    )*NN + n] = g_x1[(size_t)(b*CC + o    )*NN + n] + a0;
        out[(size_t)(b*CC + o + 1)*NN + n] = g_x1[(size_t)(b*CC + o + 1)*NN + n] + a1;
        out[(size_t)(b*CC + o + 2)*NN + n] = g_x1[(size_t)(b*CC + o + 2)*NN + n] + a2;
        out[(size_t)(b*CC + o + 3)*NN + n] = g_x1[(size_t)(b*CC + o + 3)*NN + n] + a3;
    }
}

// ---------------------------------------------------------------------------
extern "C" void kernel_launch(void* const* d_in, const int* in_sizes, int n_in,
                              void* d_out, int out_size)
{
    const float* x    = (const float*)d_in[0];
    const float* ln1w = (const float*)d_in[1];
    const float* ln1b = (const float*)d_in[2];
    const float* ln2w = (const float*)d_in[3];
    const float* ln2b = (const float*)d_in[4];
    const float* qw   = (const float*)d_in[5];
    const float* qb   = (const float*)d_in[6];
    const float* kw   = (const float*)d_in[7];
    const float* kb   = (const float*)d_in[8];
    const float* vw   = (const float*)d_in[9];
    const float* vb   = (const float*)d_in[10];
    const float* fftw = (const float*)d_in[11];
    const float* piw  = (const float*)d_in[12];
    const float* dww  = (const float*)d_in[13];
    const float* poww = (const float*)d_in[14];
    float* out = (float*)d_out;

    const int attn_smem = (5 * 64 * 64) * (int)sizeof(__half);
    cudaFuncSetAttribute(k_attn, cudaFuncAttributeMaxDynamicSharedMemorySize, attn_smem);

    k_spec<<<1, 64>>>(fftw);
    k_ln_qkv<<<BN/128, 256>>>(x, ln1w, ln1b, qw, qb, kw, kb, vw, vb);
    k_attn<<<dim3(NN/64, BB, KSPL), 128, attn_smem>>>();
    k_res_ln_proj<<<BN/128, 128>>>(x, ln2w, ln2b, piw);
    k_fftconv<<<BB*144, 512>>>();
    k_final<<<BN/128, 256>>>(dww, poww, out);
}

// round 16
// speedup vs baseline: 1.6326x; 1.0967x over previous
#include <cuda_runtime.h>
#include <cuda_fp16.h>
#include <cstdint>
#include <math.h>

#define BB 2
#define CC 64
#define HH 96
#define WIMG 96
#define NN 9216
#define BN (BB*NN)
#define NI 144
#define KSPL 2
#define IPS (NI/KSPL)    // 72 iters per split

__device__ __align__(16) __half g_q[BB*NN*CC];   // pre-scaled by log2(e)
__device__ __align__(16) __half g_k[BB*NN*CC];
__device__ __align__(16) __half g_v[BB*NN*CC];
__device__ __align__(16) float  g_oP[KSPL*BB*NN*CC];  // partial O (unnormalized)
__device__ __align__(16) float  g_lP[KSPL*BB*NN];     // partial row sums
__device__ __align__(16) float  g_x1[BB*CC*NN];
__device__ __align__(16) float  g_h [BB*CC*NN];
__device__ __align__(16) float  g_h2[BB*CC*NN];
__device__               float  g_gk[CC*64];

// ---------------- Kernel 0: spectral filter -> 8x8 circular kernel ---------
__global__ void k_spec(const float* __restrict__ fw)
{
    int c = threadIdx.x;
    const float ct[8] = {1.f, 0.70710678118654752f, 0.f, -0.70710678118654752f,
                        -1.f, -0.70710678118654752f, 0.f, 0.70710678118654752f};
    const float st[8] = {0.f, 0.70710678118654752f, 1.f, 0.70710678118654752f,
                         0.f, -0.70710678118654752f, -1.f, -0.70710678118654752f};
    float Cv[5][8], Sv[5][8];
    for (int v = 0; v < 5; v++)
        for (int d = 0; d < 8; d++) {
            float cs = 0.f, sn = 0.f;
            for (int u = 0; u < 8; u++) {
                float w = fw[c*40 + u*5 + v];
                int k = (u*d) & 7;
                cs += w * ct[k]; sn += w * st[k];
            }
            Cv[v][d] = cs; Sv[v][d] = sn;
        }
    for (int d = 0; d < 8; d++)
        for (int e = 0; e < 8; e++) {
            float acc = Cv[0][d] + ((e & 1) ? -Cv[4][d] : Cv[4][d]);
            for (int v = 1; v <= 3; v++) {
                int k = (v*e) & 7;
                acc += 2.f * (Cv[v][d]*ct[k] - Sv[v][d]*st[k]);
            }
            g_gk[c*64 + d*8 + e] = acc * (1.f/64.f);
        }
}

// ---------------- Kernel 1: LN1 + QKV (q scaled by log2 e) -----------------
__global__ void __launch_bounds__(256) k_ln_qkv(const float* __restrict__ x,
    const float* __restrict__ lnw, const float* __restrict__ lnb,
    const float* __restrict__ qw, const float* __restrict__ qb,
    const float* __restrict__ kw, const float* __restrict__ kb,
    const float* __restrict__ vw, const float* __restrict__ vb)
{
    __shared__ float sW[CC*CC];
    __shared__ float sB[CC], sLw[CC], sLb[CC];
    int tid = threadIdx.x;
    if (tid < CC) { sLw[tid] = lnw[tid]; sLb[tid] = lnb[tid]; }
    __syncthreads();
    int p = blockIdx.x * 128 + (tid >> 1);
    int hf = tid & 1;
    int b = p / NN, n = p % NN;
    const float* xb = x + (size_t)b * CC * NN + n;
    float xv[CC];
    float mu = 0.f;
#pragma unroll
    for (int c = 0; c < CC; c++) { xv[c] = xb[(size_t)c * NN]; mu += xv[c]; }
    mu *= (1.f / CC);
    float var = 0.f;
#pragma unroll
    for (int c = 0; c < CC; c++) { float d = xv[c] - mu; var += d * d; }
    float rstd = rsqrtf(var * (1.f / CC) + 1e-5f);
#pragma unroll
    for (int c = 0; c < CC; c++) xv[c] = (xv[c] - mu) * rstd * sLw[c] + sLb[c];

    const float* Wp[3] = {qw, kw, vw};
    const float* Bp[3] = {qb, kb, vb};
    __half* Op[3] = {g_q, g_k, g_v};
    int obase = hf * 32;
#pragma unroll 1
    for (int m = 0; m < 3; m++) {
        __syncthreads();
        for (int i = tid; i < CC*CC; i += 256) sW[i] = Wp[m][i];
        if (tid < CC) sB[tid] = Bp[m][tid];
        __syncthreads();
        float sc = (m == 0) ? 1.4426950408889634f : 1.0f;
        __half2* op = (__half2*)(Op[m] + (size_t)p * CC);
#pragma unroll 1
        for (int oo = 0; oo < 32; oo += 4) {
            int o = obase + oo;
            float a0 = sB[o], a1 = sB[o+1], a2 = sB[o+2], a3 = sB[o+3];
            const float4* w0 = (const float4*)&sW[(o  ) * CC];
            const float4* w1 = (const float4*)&sW[(o+1) * CC];
            const float4* w2 = (const float4*)&sW[(o+2) * CC];
            const float4* w3 = (const float4*)&sW[(o+3) * CC];
#pragma unroll
            for (int c4 = 0; c4 < 16; c4++) {
                int c = c4 * 4;
                float4 v0 = w0[c4], v1 = w1[c4], v2 = w2[c4], v3 = w3[c4];
                a0 = fmaf(v0.x, xv[c], a0); a0 = fmaf(v0.y, xv[c+1], a0);
                a0 = fmaf(v0.z, xv[c+2], a0); a0 = fmaf(v0.w, xv[c+3], a0);
                a1 = fmaf(v1.x, xv[c], a1); a1 = fmaf(v1.y, xv[c+1], a1);
                a1 = fmaf(v1.z, xv[c+2], a1); a1 = fmaf(v1.w, xv[c+3], a1);
                a2 = fmaf(v2.x, xv[c], a2); a2 = fmaf(v2.y, xv[c+1], a2);
                a2 = fmaf(v2.z, xv[c+2], a2); a2 = fmaf(v2.w, xv[c+3], a2);
                a3 = fmaf(v3.x, xv[c], a3); a3 = fmaf(v3.y, xv[c+1], a3);
                a3 = fmaf(v3.z, xv[c+2], a3); a3 = fmaf(v3.w, xv[c+3], a3);
            }
            op[(o >> 1)    ] = __floats2half2_rn(a0 * sc, a1 * sc);
            op[(o >> 1) + 1] = __floats2half2_rn(a2 * sc, a3 * sc);
        }
    }
}

// ---------------- Kernel 2: flash attention, f16-acc QK, occ 4 (R11) -------
__device__ __forceinline__ uint32_t smem_u32(const void* p) {
    return (uint32_t)__cvta_generic_to_shared(p);
}
__device__ __forceinline__ void cp16(uint32_t dst, const void* src) {
    asm volatile("cp.async.cg.shared.global [%0], [%1], 16;\n" :: "r"(dst), "l"(src));
}
__device__ __forceinline__ int swz(int row, int col) {
    int chunk = col >> 3;
    return row * 64 + ((chunk ^ (row & 7)) << 3) + (col & 7);
}

__global__ void __launch_bounds__(128, 4) k_attn()
{
    extern __shared__ __align__(16) __half smem[];
    __half* sQ = smem;                 // 64*64 swizzled
    __half* sK = smem + 64*64;         // 2 stages x 64*64
    __half* sV = sK + 2*64*64;         // 2 stages x 64*64

    int tid = threadIdx.x;
    int w = tid >> 5, lane = tid & 31;
    int b = blockIdx.y;
    int ks = blockIdx.z;
    int q0 = blockIdx.x * 64;
    int it0 = ks * IPS, itE = it0 + IPS;

    {
        const uint4* gq = (const uint4*)(g_q + ((size_t)b * NN + q0) * CC);
#pragma unroll
        for (int j = 0; j < 4; j++) {
            int i = tid + 128 * j; int r = i >> 3, cbk = i & 7;
            *(uint4*)(sQ + r*64 + ((cbk ^ (r & 7)) << 3)) = gq[i];
        }
    }

    auto prefetch = [&](int t, int st) {
        const char* gk = (const char*)(g_k + ((size_t)b * NN + (size_t)t * 64) * CC);
        const char* gv = (const char*)(g_v + ((size_t)b * NN + (size_t)t * 64) * CC);
        uint32_t kb = smem_u32(sK + st*64*64);
        uint32_t vb = smem_u32(sV + st*64*64);
#pragma unroll
        for (int j = 0; j < 4; j++) {
            int i = tid + 128 * j; int r = i >> 3, cbk = i & 7;
            int off = (r*64 + ((cbk ^ (r & 7)) << 3)) * 2;
            cp16(kb + off, gk + i*16);
            cp16(vb + off, gv + i*16);
        }
        asm volatile("cp.async.commit_group;\n" ::: "memory");
    };
    prefetch(it0, 0);
    prefetch(it0 + 1, 1);
    __syncthreads();

    uint32_t qa[4][4];
    {
        int g8_ = lane & 7;
        int sel_ = lane >> 3;
        int radd = (sel_ & 1) ? 8 : 0;
        int cadd = (sel_ & 2) ? 8 : 0;
#pragma unroll
        for (int kt = 0; kt < 4; kt++) {
            int row = w*16 + radd + g8_;
            int col = kt*16 + cadd;
            uint32_t a = smem_u32(sQ + swz(row, col));
            asm volatile("ldmatrix.sync.aligned.m8n8.x4.shared.b16 {%0,%1,%2,%3},[%4];"
                : "=r"(qa[kt][0]), "=r"(qa[kt][1]), "=r"(qa[kt][2]), "=r"(qa[kt][3])
                : "r"(a));
        }
    }

    float o[8][4];
    float lacc0 = 0.f, lacc1 = 0.f;
#pragma unroll
    for (int i = 0; i < 8; i++)
#pragma unroll
        for (int j = 0; j < 4; j++) o[i][j] = 0.f;

    int g8 = lane & 7;
    int sel = lane >> 3;
    int sel2 = lane >> 4;
    const uint32_t BIAS8 = 0xC800C800u;   // f16x2 {-8, -8}

#pragma unroll 1
    for (int it = it0; it < itE; it++) {
        if (it + 1 < itE) asm volatile("cp.async.wait_group 1;" ::: "memory");
        else              asm volatile("cp.async.wait_group 0;" ::: "memory");
        __syncthreads();
        const __half* bK = sK + (it & 1) * 64*64;
        const __half* bV = sV + (it & 1) * 64*64;

        uint32_t sh[8][2];
#pragma unroll
        for (int nt = 0; nt < 8; nt++) { sh[nt][0] = 0u; sh[nt][1] = 0u; }
#pragma unroll
        for (int kk = 0; kk < 4; kk++) {
#pragma unroll
            for (int ntp = 0; ntp < 4; ntp++) {
                uint32_t b0, b1, b2, b3;
                int row = (2*ntp + (sel >> 1))*8 + g8;
                int col = kk*16 + (sel & 1)*8;
                uint32_t a = smem_u32(bK + swz(row, col));
                asm volatile("ldmatrix.sync.aligned.m8n8.x4.shared.b16 {%0,%1,%2,%3},[%4];"
                    : "=r"(b0), "=r"(b1), "=r"(b2), "=r"(b3) : "r"(a));
                asm volatile("mma.sync.aligned.m16n8k16.row.col.f16.f16.f16.f16 "
                    "{%0,%1},{%2,%3,%4,%5},{%6,%7},{%0,%1};"
                    : "+r"(sh[2*ntp][0]), "+r"(sh[2*ntp][1])
                    : "r"(qa[kk][0]), "r"(qa[kk][1]), "r"(qa[kk][2]), "r"(qa[kk][3]),
                      "r"(b0), "r"(b1));
                asm volatile("mma.sync.aligned.m16n8k16.row.col.f16.f16.f16.f16 "
                    "{%0,%1},{%2,%3,%4,%5},{%6,%7},{%0,%1};"
                    : "+r"(sh[2*ntp+1][0]), "+r"(sh[2*ntp+1][1])
                    : "r"(qa[kk][0]), "r"(qa[kk][1]), "r"(qa[kk][2]), "r"(qa[kk][3]),
                      "r"(b2), "r"(b3));
            }
        }

        uint32_t ph[8][2];
        uint32_t a0h = 0, a1h = 0;
#pragma unroll
        for (int nt = 0; nt < 8; nt++) {
            uint32_t r01, r23;
            asm("add.rn.f16x2 %0, %1, %2;" : "=r"(r01) : "r"(sh[nt][0]), "r"(BIAS8));
            asm("add.rn.f16x2 %0, %1, %2;" : "=r"(r23) : "r"(sh[nt][1]), "r"(BIAS8));
            asm("ex2.approx.f16x2 %0, %1;" : "=r"(r01) : "r"(r01));
            asm("ex2.approx.f16x2 %0, %1;" : "=r"(r23) : "r"(r23));
            ph[nt][0] = r01; ph[nt][1] = r23;
            asm("add.rn.f16x2 %0, %0, %1;" : "+r"(a0h) : "r"(r01));
            asm("add.rn.f16x2 %0, %0, %1;" : "+r"(a1h) : "r"(r23));
        }
        {
            float2 f0 = __half22float2(*(__half2*)&a0h);
            float2 f1 = __half22float2(*(__half2*)&a1h);
            lacc0 += f0.x + f0.y;
            lacc1 += f1.x + f1.y;
        }

#pragma unroll
        for (int kt = 0; kt < 4; kt++) {
            uint32_t a0 = ph[2*kt][0], a1 = ph[2*kt][1];
            uint32_t a2 = ph[2*kt+1][0], a3 = ph[2*kt+1][1];
#pragma unroll
            for (int ntp = 0; ntp < 4; ntp++) {
                uint32_t b0, b1, b2, b3;
                int row = kt*16 + (lane & 15);
                int col = (2*ntp + sel2)*8;
                uint32_t a = smem_u32(bV + swz(row, col));
                asm volatile("ldmatrix.sync.aligned.m8n8.x4.trans.shared.b16 {%0,%1,%2,%3},[%4];"
                    : "=r"(b0), "=r"(b1), "=r"(b2), "=r"(b3) : "r"(a));
                asm volatile("mma.sync.aligned.m16n8k16.row.col.f32.f16.f16.f32 "
                    "{%0,%1,%2,%3},{%4,%5,%6,%7},{%8,%9},{%0,%1,%2,%3};"
                    : "+f"(o[2*ntp][0]), "+f"(o[2*ntp][1]), "+f"(o[2*ntp][2]), "+f"(o[2*ntp][3])
                    : "r"(a0), "r"(a1), "r"(a2), "r"(a3), "r"(b0), "r"(b1));
                asm volatile("mma.sync.aligned.m16n8k16.row.col.f32.f16.f16.f32 "
                    "{%0,%1,%2,%3},{%4,%5,%6,%7},{%8,%9},{%0,%1,%2,%3};"
                    : "+f"(o[2*ntp+1][0]), "+f"(o[2*ntp+1][1]), "+f"(o[2*ntp+1][2]), "+f"(o[2*ntp+1][3])
                    : "r"(a0), "r"(a1), "r"(a2), "r"(a3), "r"(b2), "r"(b3));
            }
        }
        __syncthreads();
        if (it + 2 < itE) prefetch(it + 2, it & 1);
    }

    lacc0 += __shfl_xor_sync(0xffffffffu, lacc0, 1);
    lacc0 += __shfl_xor_sync(0xffffffffu, lacc0, 2);
    lacc1 += __shfl_xor_sync(0xffffffffu, lacc1, 1);
    lacc1 += __shfl_xor_sync(0xffffffffu, lacc1, 2);
    int g = lane >> 2, qd = lane & 3;
    int row0 = q0 + w*16 + g;
    int row1 = row0 + 8;
    float* Ob = g_oP + ((size_t)(ks*BB + b) * NN) * CC;
#pragma unroll
    for (int nt = 0; nt < 8; nt++) {
        int c = nt*8 + 2*qd;
        *(float2*)&Ob[(size_t)row0*CC + c] = make_float2(o[nt][0], o[nt][1]);
        *(float2*)&Ob[(size_t)row1*CC + c] = make_float2(o[nt][2], o[nt][3]);
    }
    if (qd == 0) {
        g_lP[(size_t)(ks*BB + b) * NN + row0] = lacc0;
        g_lP[(size_t)(ks*BB + b) * NN + row1] = lacc1;
    }
}

// ---------------- Kernel 3: merge partials + residual + LN2 + proj_in ------
__global__ void k_res_ln_proj(const float* __restrict__ x,
    const float* __restrict__ lnw, const float* __restrict__ lnb,
    const float* __restrict__ pw)
{
    __shared__ float sW[CC*CC];
    __shared__ float sLw[CC], sLb[CC];
    int tid = threadIdx.x;
    for (int i = tid; i < CC*CC; i += 128) sW[i] = pw[i];
    if (tid < CC) { sLw[tid] = lnw[tid]; sLb[tid] = lnb[tid]; }
    __syncthreads();
    int p = blockIdx.x * 128 + tid;
    int b = p / NN, n = p % NN;
    const float4* oA = (const float4*)(g_oP + (size_t)(0*BB + b) * NN * CC + (size_t)n * CC);
    const float4* oB = (const float4*)(g_oP + (size_t)(1*BB + b) * NN * CC + (size_t)n * CC);
    float invl = 1.f / (g_lP[(size_t)(0*BB + b)*NN + n] + g_lP[(size_t)(1*BB + b)*NN + n]);
    const float* xb = x + (size_t)b * CC * NN + n;
    float* x1b = g_x1 + (size_t)b * CC * NN + n;
    float xv[CC];
    float mu = 0.f;
#pragma unroll
    for (int c4 = 0; c4 < CC/4; c4++) {
        float4 va = oA[c4], vb = oB[c4];
        int c = c4 * 4;
        float t0 = xb[(size_t)(c+0)*NN] + (va.x + vb.x) * invl;
        float t1 = xb[(size_t)(c+1)*NN] + (va.y + vb.y) * invl;
        float t2 = xb[(size_t)(c+2)*NN] + (va.z + vb.z) * invl;
        float t3 = xb[(size_t)(c+3)*NN] + (va.w + vb.w) * invl;
        x1b[(size_t)(c+0)*NN] = t0; x1b[(size_t)(c+1)*NN] = t1;
        x1b[(size_t)(c+2)*NN] = t2; x1b[(size_t)(c+3)*NN] = t3;
        xv[c+0]=t0; xv[c+1]=t1; xv[c+2]=t2; xv[c+3]=t3;
        mu += t0 + t1 + t2 + t3;
    }
    mu *= (1.f / CC);
    float var = 0.f;
#pragma unroll
    for (int c = 0; c < CC; c++) { float d = xv[c] - mu; var += d * d; }
    float rstd = rsqrtf(var * (1.f / CC) + 1e-5f);
#pragma unroll
    for (int c = 0; c < CC; c++) xv[c] = (xv[c] - mu) * rstd * sLw[c] + sLb[c];

    float* hb = g_h + (size_t)b * CC * NN + n;
#pragma unroll 1
    for (int o = 0; o < CC; o += 4) {
        float a0 = 0.f, a1 = 0.f, a2 = 0.f, a3 = 0.f;
        const float4* w0 = (const float4*)&sW[(o  ) * CC];
        const float4* w1 = (const float4*)&sW[(o+1) * CC];
        const float4* w2 = (const float4*)&sW[(o+2) * CC];
        const float4* w3 = (const float4*)&sW[(o+3) * CC];
#pragma unroll
        for (int c4 = 0; c4 < 16; c4++) {
            int c = c4 * 4;
            float4 v0 = w0[c4], v1 = w1[c4], v2 = w2[c4], v3 = w3[c4];
            a0 = fmaf(v0.x, xv[c], a0); a0 = fmaf(v0.y, xv[c+1], a0);
            a0 = fmaf(v0.z, xv[c+2], a0); a0 = fmaf(v0.w, xv[c+3], a0);
            a1 = fmaf(v1.x, xv[c], a1); a1 = fmaf(v1.y, xv[c+1], a1);
            a1 = fmaf(v1.z, xv[c+2], a1); a1 = fmaf(v1.w, xv[c+3], a1);
            a2 = fmaf(v2.x, xv[c], a2); a2 = fmaf(v2.y, xv[c+1], a2);
            a2 = fmaf(v2.z, xv[c+2], a2); a2 = fmaf(v2.w, xv[c+3], a2);
            a3 = fmaf(v3.x, xv[c], a3); a3 = fmaf(v3.y, xv[c+1], a3);
            a3 = fmaf(v3.z, xv[c+2], a3); a3 = fmaf(v3.w, xv[c+3], a3);
        }
        hb[(size_t)(o+0)*NN] = a0;
        hb[(size_t)(o+1)*NN] = a1;
        hb[(size_t)(o+2)*NN] = a2;
        hb[(size_t)(o+3)*NN] = a3;
    }
}

// ---------------- Kernel 4: per-patch 8x8 circular conv, register-blocked --
__global__ void __launch_bounds__(512) k_fftconv()
{
    __shared__ float sin_[CC*72];
    __shared__ float sg[CC*72];
    int tid = threadIdx.x;
    int blk = blockIdx.x;
    int b = blk / 144;
    int pr = (blk / 12) % 12, pc = blk % 12;
    for (int i = tid; i < CC*64; i += 512) {
        int c = i >> 6, pos = i & 63;
        int y = pr*8 + (pos >> 3), x = pc*8 + (pos & 7);
        sin_[c*72 + pos] = g_h[(size_t)(b*CC + c)*NN + y*WIMG + x];
        sg[c*72 + pos] = g_gk[i];
    }
    __syncthreads();

    int c = tid >> 3;
    int n = tid & 7;
    float acc[8];
#pragma unroll
    for (int m = 0; m < 8; m++) acc[m] = 0.f;

#pragma unroll
    for (int pp = 0; pp < 8; pp++) {
        int grow = (n - pp) & 7;
        const float* gr = &sg[c*72 + grow*8];
        float gv[8] = {gr[0], gr[1], gr[2], gr[3], gr[4], gr[5], gr[6], gr[7]};
        const float* ir = &sin_[c*72 + pp*8];
#pragma unroll
        for (int qq = 0; qq < 8; qq++) {
            float iv = ir[qq];
#pragma unroll
            for (int m = 0; m < 8; m++)
                acc[m] = fmaf(iv, gv[(m - qq) & 7], acc[m]);
        }
    }

    int y = pr*8 + n;
    float* dst = &g_h2[(size_t)(b*CC + c)*NN + y*WIMG + pc*8];
    *(float4*)(dst    ) = make_float4(acc[0], acc[1], acc[2], acc[3]);
    *(float4*)(dst + 4) = make_float4(acc[4], acc[5], acc[6], acc[7]);
}

// ---------------- Kernel 5: dw3x3 + GELU gate + proj_out, gate pair-split --
__device__ __forceinline__ float dw3x3(const float* __restrict__ base,
                                       int y, int x, const float* __restrict__ w9)
{
    float acc = 0.f;
#pragma unroll
    for (int dy = -1; dy <= 1; dy++) {
        int yy = y + dy;
        if ((unsigned)yy >= HH) continue;
#pragma unroll
        for (int dx = -1; dx <= 1; dx++) {
            int xx = x + dx;
            if ((unsigned)xx >= WIMG) continue;
            acc = fmaf(base[yy*WIMG + xx], w9[(dy+1)*3 + (dx+1)], acc);
        }
    }
    return acc;
}

__global__ void __launch_bounds__(256) k_final(const float* __restrict__ dw,
                        const float* __restrict__ pw,
                        float* __restrict__ out)
{
    __shared__ float sW[CC*32];
    __shared__ float sD[CC*9];
    int tid = threadIdx.x;
    for (int i = tid; i < CC*32; i += 256) sW[i] = pw[i];
    for (int i = tid; i < CC*9; i += 256) sD[i] = dw[i];
    __syncthreads();
    int p = blockIdx.x * 128 + (tid >> 1);
    int hf = tid & 1;
    int b = p / NN, n = p % NN;
    int y = n / WIMG, x = n % WIMG;

    // each pair-thread computes 16 of the 32 gate channels
    int gc0 = hf * 16;
    float gvo[16];
#pragma unroll
    for (int j = 0; j < 16; j++) {
        int c = gc0 + j;
        const float* b1 = g_h2 + (size_t)(b*CC + c) * NN;
        const float* b2 = g_h2 + (size_t)(b*CC + c + 32) * NN;
        float h1 = dw3x3(b1, y, x, &sD[c*9]);
        float h2 = dw3x3(b2, y, x, &sD[(c+32)*9]);
        float gl = 0.5f * h1 * (1.f + erff(h1 * 0.70710678118654752f));
        gvo[j] = gl * h2;
    }
    float gvp[16];
#pragma unroll
    for (int j = 0; j < 16; j++) gvp[j] = __shfl_xor_sync(0xffffffffu, gvo[j], 1);

    int obase = hf * 32;
    int pc0 = gc0 ^ 16;   // partner's gate-channel base
#pragma unroll 1
    for (int oo = 0; oo < 32; oo += 4) {
        int o = obase + oo;
        float a0 = 0.f, a1 = 0.f, a2 = 0.f, a3 = 0.f;
        const float4* w0o = (const float4*)&sW[(o  ) * 32 + gc0];
        const float4* w1o = (const float4*)&sW[(o+1) * 32 + gc0];
        const float4* w2o = (const float4*)&sW[(o+2) * 32 + gc0];
        const float4* w3o = (const float4*)&sW[(o+3) * 32 + gc0];
        const float4* w0p = (const float4*)&sW[(o  ) * 32 + pc0];
        const float4* w1p = (const float4*)&sW[(o+1) * 32 + pc0];
        const float4* w2p = (const float4*)&sW[(o+2) * 32 + pc0];
        const float4* w3p = (const float4*)&sW[(o+3) * 32 + pc0];
#pragma unroll
        for (int c4 = 0; c4 < 4; c4++) {
            int c = c4 * 4;
            float4 v0 = w0o[c4], v1 = w1o[c4], v2 = w2o[c4], v3 = w3o[c4];
            a0 = fmaf(v0.x, gvo[c], a0); a0 = fmaf(v0.y, gvo[c+1], a0);
            a0 = fmaf(v0.z, gvo[c+2], a0); a0 = fmaf(v0.w, gvo[c+3], a0);
            a1 = fmaf(v1.x, gvo[c], a1); a1 = fmaf(v1.y, gvo[c+1], a1);
            a1 = fmaf(v1.z, gvo[c+2], a1); a1 = fmaf(v1.w, gvo[c+3], a1);
            a2 = fmaf(v2.x, gvo[c], a2); a2 = fmaf(v2.y, gvo[c+1], a2);
            a2 = fmaf(v2.z, gvo[c+2], a2); a2 = fmaf(v2.w, gvo[c+3], a2);
            a3 = fmaf(v3.x, gvo[c], a3); a3 = fmaf(v3.y, gvo[c+1], a3);
            a3 = fmaf(v3.z, gvo[c+2], a3); a3 = fmaf(v3.w, gvo[c+3], a3);
            float4 u0 = w0p[c4], u1 = w1p[c4], u2 = w2p[c4], u3 = w3p[c4];
            a0 = fmaf(u0.x, gvp[c], a0); a0 = fmaf(u0.y, gvp[c+1], a0);
            a0 = fmaf(u0.z, gvp[c+2], a0); a0 = fmaf(u0.w, gvp[c+3], a0);
            a1 = fmaf(u1.x, gvp[c], a1); a1 = fmaf(u1.y, gvp[c+1], a1);
            a1 = fmaf(u1.z, gvp[c+2], a1); a1 = fmaf(u1.w, gvp[c+3], a1);
            a2 = fmaf(u2.x, gvp[c], a2); a2 = fmaf(u2.y, gvp[c+1], a2);
            a2 = fmaf(u2.z, gvp[c+2], a2); a2 = fmaf(u2.w, gvp[c+3], a2);
            a3 = fmaf(u3.x, gvp[c], a3); a3 = fmaf(u3.y, gvp[c+1], a3);
            a3 = fmaf(u3.z, gvp[c+2], a3); a3 = fmaf(u3.w, gvp[c+3], a3);
        }
        out[(size_t)(b*CC + o    )*NN + n] = g_x1[(size_t)(b*CC + o    )*NN + n] + a0;
        out[(size_t)(b*CC + o + 1)*NN + n] = g_x1[(size_t)(b*CC + o + 1)*NN + n] + a1;
        out[(size_t)(b*CC + o + 2)*NN + n] = g_x1[(size_t)(b*CC + o + 2)*NN + n] + a2;
        out[(size_t)(b*CC + o + 3)*NN + n] = g_x1[(size_t)(b*CC + o + 3)*NN + n] + a3;
    }
}

// ---------------------------------------------------------------------------
extern "C" void kernel_launch(void* const* d_in, const int* in_sizes, int n_in,
                              void* d_out, int out_size)
{
    const float* x    = (const float*)d_in[0];
    const float* ln1w = (const float*)d_in[1];
    const float* ln1b = (const float*)d_in[2];
    const float* ln2w = (const float*)d_in[3];
    const float* ln2b = (const float*)d_in[4];
    const float* qw   = (const float*)d_in[5];
    const float* qb   = (const float*)d_in[6];
    const float* kw   = (const float*)d_in[7];
    const float* kb   = (const float*)d_in[8];
    const float* vw   = (const float*)d_in[9];
    const float* vb   = (const float*)d_in[10];
    const float* fftw = (const float*)d_in[11];
    const float* piw  = (const float*)d_in[12];
    const float* dww  = (const float*)d_in[13];
    const float* poww = (const float*)d_in[14];
    float* out = (float*)d_out;

    const int attn_smem = (5 * 64 * 64) * (int)sizeof(__half);
    cudaFuncSetAttribute(k_attn, cudaFuncAttributeMaxDynamicSharedMemorySize, attn_smem);

    k_spec<<<1, 64>>>(fftw);
    k_ln_qkv<<<BN/128, 256>>>(x, ln1w, ln1b, qw, qb, kw, kb, vw, vb);
    k_attn<<<dim3(NN/64, BB, KSPL), 128, attn_smem>>>();
    k_res_ln_proj<<<BN/128, 128>>>(x, ln2w, ln2b, piw);
    k_fftconv<<<BB*144, 512>>>();
    k_final<<<BN/128, 256>>>(dww, poww, out);
}